// round 1
// baseline (speedup 1.0000x reference)
#include <cuda_runtime.h>
#include <math.h>

#define NROWS 6144
#define DIM 128
#define WINSZ 10
#define BANDW 21
#define NEMO 7
#define YCOLS 640   // [W_pred | W_suc | W_same | W_diff | w_aggr] * 128

// ---------------- scratch (device globals; no allocation allowed) ------------
__device__ float g_attn[NROWS * BANDW];       // banded softmax attn
__device__ float g_Wcat1[DIM * YCOLS];        // packed layer-1 weights
__device__ float g_Wcat2[DIM * YCOLS];        // packed layer-2 weights
__device__ float g_Y[NROWS * YCOLS];          // h @ Wcat
__device__ float g_H1[NROWS * DIM];           // layer-1 output
__device__ float g_Hcat[NROWS * 2 * DIM];     // [h2 | x]
__device__ float g_T[NROWS * DIM];            // relu(Hcat @ w_e1 + b_e1)

__device__ float* buf_ptr(int id) {
    switch (id) {
        case 1: return g_Y;
        case 2: return g_H1;
        case 3: return g_Hcat;
        case 4: return g_T;
        case 5: return g_Wcat1;
        case 6: return g_Wcat2;
    }
    return nullptr;
}

// ---------------- kernel: copy x into right half of Hcat ---------------------
__global__ void copyx_kernel(const float* __restrict__ x) {
    int idx = blockIdx.x * blockDim.x + threadIdx.x;
    if (idx >= NROWS * DIM) return;
    int i = idx >> 7, d = idx & 127;
    g_Hcat[i * 2 * DIM + DIM + d] = x[idx];
}

// ---------------- kernel: banded scores + faithful softmax -------------------
// Row i: scores s_ij = x_i . x_j for |i-j|<=WIN, other entries are literal 0.0
// m = max(band scores, 0); den = sum_band exp(s-m) + (N-nband)*exp(-m)
// attn band stored [N][21], l = j-(i-WIN). Out-of-band attn = exp(-m)/den
// ~ 1e-38 -> contributes ~1e-29 to outputs, neglected (fp32 reference
// underflows identically in spirit; far below 1e-3 tolerance).
__global__ void attn_kernel(const float* __restrict__ x) {
    int warp = threadIdx.x >> 5;
    int lane = threadIdx.x & 31;
    int i = blockIdx.x * 4 + warp;
    if (i >= NROWS) return;

    float xi0 = x[i * DIM + lane];
    float xi1 = x[i * DIM + 32 + lane];
    float xi2 = x[i * DIM + 64 + lane];
    float xi3 = x[i * DIM + 96 + lane];

    float myscore = -3.4e38f;
    #pragma unroll
    for (int l = 0; l < BANDW; l++) {
        int j = i - WINSZ + l;
        if (j >= 0 && j < NROWS) {
            const float* xj = x + (size_t)j * DIM;
            float s = xi0 * xj[lane] + xi1 * xj[32 + lane]
                    + xi2 * xj[64 + lane] + xi3 * xj[96 + lane];
            #pragma unroll
            for (int off = 16; off; off >>= 1) s += __shfl_xor_sync(~0u, s, off);
            if (lane == l) myscore = s;
        }
    }
    int jl = i - WINSZ + lane;
    bool valid = (lane < BANDW) && (jl >= 0) && (jl < NROWS);
    float m = valid ? myscore : -3.4e38f;
    #pragma unroll
    for (int off = 16; off; off >>= 1) m = fmaxf(m, __shfl_xor_sync(~0u, m, off));
    m = fmaxf(m, 0.0f);
    float e = valid ? expf(myscore - m) : 0.0f;
    float sum = e;
    #pragma unroll
    for (int off = 16; off; off >>= 1) sum += __shfl_xor_sync(~0u, sum, off);
    int lo = max(0, i - WINSZ), hi = min(NROWS - 1, i + WINSZ);
    int nband = hi - lo + 1;
    float den = sum + (float)(NROWS - nband) * expf(-m);
    if (lane < BANDW) g_attn[i * BANDW + lane] = e / den;
}

// ---------------- kernel: pack per-layer weights into [128][640] -------------
__global__ void pack_kernel(const float* __restrict__ Wp1, const float* __restrict__ Ws1,
                            const float* __restrict__ Wsa1, const float* __restrict__ Wd1,
                            const float* __restrict__ Wag1,
                            const float* __restrict__ Wp2, const float* __restrict__ Ws2,
                            const float* __restrict__ Wsa2, const float* __restrict__ Wd2,
                            const float* __restrict__ Wag2) {
    int idx = blockIdx.x * blockDim.x + threadIdx.x;
    if (idx >= DIM * YCOLS) return;
    int k = idx / YCOLS, c = idx % YCOLS;
    int rel = c >> 7, d = c & 127;
    const float* s1;
    const float* s2;
    switch (rel) {
        case 0: s1 = Wp1;  s2 = Wp2;  break;
        case 1: s1 = Ws1;  s2 = Ws2;  break;
        case 2: s1 = Wsa1; s2 = Wsa2; break;
        case 3: s1 = Wd1;  s2 = Wd2;  break;
        default: s1 = Wag1; s2 = Wag2; break;
    }
    g_Wcat1[idx] = s1[k * DIM + d];
    g_Wcat2[idx] = s2[k * DIM + d];
}

// ---------------- kernel: tiled SGEMM (BM=BN=64, BK=32, 4x4/thread) ----------
template <bool RELU, bool BIAS>
__global__ void sgemm_kernel(const float* __restrict__ Ax, int Aid,
                             const float* __restrict__ Bx, int Bid,
                             const float* __restrict__ bias,
                             float* __restrict__ Cx, int Cid,
                             int M, int N, int K) {
    const float* A = Ax ? Ax : buf_ptr(Aid);
    const float* B = Bx ? Bx : buf_ptr(Bid);
    float* C = Cx ? Cx : buf_ptr(Cid);

    __shared__ float As[64][36];   // [m][k], row stride 144B keeps float4 align
    __shared__ float Bs[32][64];   // [k][n]

    int tid = threadIdx.x;
    int tx = tid & 15, ty = tid >> 4;
    int bm = blockIdx.y * 64;
    int bn = blockIdx.x * 64;

    float acc[4][4] = {};
    for (int k0 = 0; k0 < K; k0 += 32) {
        {   // A tile 64x32
            int r = tid >> 3;
            int c = (tid & 7) << 2;
            float4 a0 = *(const float4*)&A[(size_t)(bm + r) * K + k0 + c];
            float4 a1 = *(const float4*)&A[(size_t)(bm + r + 32) * K + k0 + c];
            *(float4*)&As[r][c] = a0;
            *(float4*)&As[r + 32][c] = a1;
        }
        {   // B tile 32x64
            int r = tid >> 4;
            int c = (tid & 15) << 2;
            float4 b0 = *(const float4*)&B[(size_t)(k0 + r) * N + bn + c];
            float4 b1 = *(const float4*)&B[(size_t)(k0 + r + 16) * N + bn + c];
            *(float4*)&Bs[r][c] = b0;
            *(float4*)&Bs[r + 16][c] = b1;
        }
        __syncthreads();
        #pragma unroll
        for (int k = 0; k < 32; k++) {
            float a[4];
            #pragma unroll
            for (int u = 0; u < 4; u++) a[u] = As[ty * 4 + u][k];
            float4 bv = *(const float4*)&Bs[k][tx * 4];
            float b[4] = {bv.x, bv.y, bv.z, bv.w};
            #pragma unroll
            for (int u = 0; u < 4; u++)
                #pragma unroll
                for (int v = 0; v < 4; v++)
                    acc[u][v] += a[u] * b[v];
        }
        __syncthreads();
    }
    #pragma unroll
    for (int u = 0; u < 4; u++) {
        int row = bm + ty * 4 + u;
        #pragma unroll
        for (int v = 0; v < 4; v++) {
            int col = bn + tx * 4 + v;
            float val = acc[u][v];
            if (BIAS) val += bias[col];
            if (RELU) val = fmaxf(val, 0.0f);
            C[(size_t)row * N + col] = val;
        }
    }
}

// ---------------- kernel: banded combine + aggr + relu -----------------------
// out_i[d] = relu( sum_{l} attn[i][l] * Y[j][sel*128+d]  +  attn[i][10]*Y[i][512+d] )
// sel: same&pred->0(W_pred), same&suc->1(W_suc), diff&pred->2(W_same), diff&suc->3(W_diff)
__global__ void combine_kernel(const int* __restrict__ spk, int outid, int out_stride) {
    float* out = buf_ptr(outid);
    int i = blockIdx.x;
    int d = threadIdx.x;   // 128 threads

    __shared__ float a_s[BANDW];
    __shared__ int off_s[BANDW];
    if (d < BANDW) {
        int j = i - WINSZ + d;
        float a = 0.0f;
        int off = 0;
        if (j >= 0 && j < NROWS) {
            a = g_attn[i * BANDW + d];
            bool same = (spk[j] == spk[i]);
            bool pred = (d >= WINSZ);      // j >= i
            int col = same ? (pred ? 0 : 1) : (pred ? 2 : 3);
            off = j * YCOLS + col * DIM;
        }
        a_s[d] = a;
        off_s[d] = off;
    }
    __syncthreads();

    float acc = a_s[WINSZ] * g_Y[i * YCOLS + 4 * DIM + d];   // diag * (h @ w_aggr)
    #pragma unroll
    for (int l = 0; l < BANDW; l++) {
        int j = i - WINSZ + l;
        if (j < 0 || j >= NROWS) continue;
        acc += a_s[l] * g_Y[off_s[l] + d];
    }
    out[(size_t)i * out_stride + d] = fmaxf(acc, 0.0f);
}

// ---------------- kernel: emotion / sentiment heads --------------------------
__global__ void head_kernel(const float* __restrict__ we2, const float* __restrict__ be2,
                            const float* __restrict__ ws, const float* __restrict__ bs,
                            float* __restrict__ out) {
    int warp = threadIdx.x >> 5, lane = threadIdx.x & 31;
    int i = blockIdx.x * 8 + warp;
    if (i >= NROWS) return;

    float tv[4];
    #pragma unroll
    for (int c = 0; c < 4; c++) tv[c] = g_T[i * DIM + c * 32 + lane];
    float hv[8];
    #pragma unroll
    for (int c = 0; c < 8; c++) hv[c] = g_Hcat[i * 2 * DIM + c * 32 + lane];

    #pragma unroll
    for (int e = 0; e < NEMO; e++) {
        float s = 0.0f;
        #pragma unroll
        for (int c = 0; c < 4; c++) s += tv[c] * we2[(c * 32 + lane) * NEMO + e];
        #pragma unroll
        for (int off = 16; off; off >>= 1) s += __shfl_xor_sync(~0u, s, off);

        float s2 = 0.0f;
        #pragma unroll
        for (int c = 0; c < 8; c++) s2 += hv[c] * ws[(c * 32 + lane) * NEMO + e];
        #pragma unroll
        for (int off = 16; off; off >>= 1) s2 += __shfl_xor_sync(~0u, s2, off);

        if (lane == 0) {
            out[i * NEMO + e] = s + be2[e];                       // emotion
            out[NROWS * NEMO + i * NEMO + e] = s2 + bs[e];        // sentiment
        }
    }
}

// -----------------------------------------------------------------------------
extern "C" void kernel_launch(void* const* d_in, const int* in_sizes, int n_in,
                              void* d_out, int out_size) {
    const float* x       = (const float*)d_in[0];
    const int*   spk     = (const int*)d_in[1];
    const float* Wp1     = (const float*)d_in[2];
    const float* Ws1     = (const float*)d_in[3];
    const float* Wsa1    = (const float*)d_in[4];
    const float* Wd1     = (const float*)d_in[5];
    const float* Wp2     = (const float*)d_in[6];
    const float* Ws2     = (const float*)d_in[7];
    const float* Wsa2    = (const float*)d_in[8];
    const float* Wd2     = (const float*)d_in[9];
    const float* Wag1    = (const float*)d_in[10];
    const float* Wag2    = (const float*)d_in[11];
    const float* we1     = (const float*)d_in[12];
    const float* be1     = (const float*)d_in[13];
    const float* we2     = (const float*)d_in[14];
    const float* be2     = (const float*)d_in[15];
    const float* wsw     = (const float*)d_in[16];
    const float* bsb     = (const float*)d_in[17];
    float* out = (float*)d_out;

    // 1. x -> Hcat[:,128:256]
    copyx_kernel<<<(NROWS * DIM + 255) / 256, 256>>>(x);
    // 2. banded softmax attention
    attn_kernel<<<NROWS / 4, 128>>>(x);
    // 3. pack weights
    pack_kernel<<<(DIM * YCOLS + 255) / 256, 256>>>(Wp1, Ws1, Wsa1, Wd1, Wag1,
                                                    Wp2, Ws2, Wsa2, Wd2, Wag2);
    // 4. Y = x @ Wcat1
    sgemm_kernel<false, false><<<dim3(YCOLS / 64, NROWS / 64), 256>>>(
        x, 0, nullptr, 5, nullptr, nullptr, 1, NROWS, YCOLS, DIM);
    // 5. h1 = relu(band-combine)
    combine_kernel<<<NROWS, DIM>>>(spk, 2, DIM);
    // 6. Y = h1 @ Wcat2
    sgemm_kernel<false, false><<<dim3(YCOLS / 64, NROWS / 64), 256>>>(
        nullptr, 2, nullptr, 6, nullptr, nullptr, 1, NROWS, YCOLS, DIM);
    // 7. h2 = relu(band-combine) -> Hcat[:,0:128]
    combine_kernel<<<NROWS, DIM>>>(spk, 3, 2 * DIM);
    // 8. T = relu(Hcat @ w_e1 + b_e1)
    sgemm_kernel<true, true><<<dim3(DIM / 64, NROWS / 64), 256>>>(
        nullptr, 3, we1, 0, be1, nullptr, 4, NROWS, DIM, 2 * DIM);
    // 9. heads
    head_kernel<<<NROWS / 8, 256>>>(we2, be2, wsw, bsb, out);
}

// round 2
// speedup vs baseline: 1.0013x; 1.0013x over previous
#include <cuda_runtime.h>
#include <math.h>

#define NROWS 6144
#define DIM 128
#define WINSZ 10
#define BANDW 21
#define NEMO 7
#define YCOLS 640   // [W_pred | W_suc | W_same | W_diff | w_aggr] * 128

// ---------------- scratch (device globals; no allocation allowed) ------------
__device__ float g_attn[NROWS * BANDW];       // banded softmax attn
__device__ float g_Wcat1[DIM * YCOLS];        // packed layer-1 weights
__device__ float g_Wcat2[DIM * YCOLS];        // packed layer-2 weights
__device__ float g_Y[NROWS * YCOLS];          // h @ Wcat
__device__ float g_H1[NROWS * DIM];           // layer-1 output
__device__ float g_Hcat[NROWS * 2 * DIM];     // [h2 | x]
__device__ float g_T[NROWS * DIM];            // relu(Hcat @ w_e1 + b_e1)

__device__ float* buf_ptr(int id) {
    switch (id) {
        case 1: return g_Y;
        case 2: return g_H1;
        case 3: return g_Hcat;
        case 4: return g_T;
        case 5: return g_Wcat1;
        case 6: return g_Wcat2;
    }
    return nullptr;
}

// ---------------- kernel: copy x into right half of Hcat ---------------------
__global__ void copyx_kernel(const float* __restrict__ x) {
    int idx = blockIdx.x * blockDim.x + threadIdx.x;
    if (idx >= NROWS * DIM) return;
    int i = idx >> 7, d = idx & 127;
    g_Hcat[i * 2 * DIM + DIM + d] = x[idx];
}

// ---------------- kernel: banded scores + faithful softmax -------------------
__global__ void attn_kernel(const float* __restrict__ x) {
    int warp = threadIdx.x >> 5;
    int lane = threadIdx.x & 31;
    int i = blockIdx.x * 4 + warp;
    if (i >= NROWS) return;

    float xi0 = x[i * DIM + lane];
    float xi1 = x[i * DIM + 32 + lane];
    float xi2 = x[i * DIM + 64 + lane];
    float xi3 = x[i * DIM + 96 + lane];

    float myscore = -3.4e38f;
    #pragma unroll
    for (int l = 0; l < BANDW; l++) {
        int j = i - WINSZ + l;
        if (j >= 0 && j < NROWS) {
            const float* xj = x + (size_t)j * DIM;
            float s = xi0 * xj[lane] + xi1 * xj[32 + lane]
                    + xi2 * xj[64 + lane] + xi3 * xj[96 + lane];
            #pragma unroll
            for (int off = 16; off; off >>= 1) s += __shfl_xor_sync(~0u, s, off);
            if (lane == l) myscore = s;
        }
    }
    int jl = i - WINSZ + lane;
    bool valid = (lane < BANDW) && (jl >= 0) && (jl < NROWS);
    float m = valid ? myscore : -3.4e38f;
    #pragma unroll
    for (int off = 16; off; off >>= 1) m = fmaxf(m, __shfl_xor_sync(~0u, m, off));
    m = fmaxf(m, 0.0f);
    float e = valid ? expf(myscore - m) : 0.0f;
    float sum = e;
    #pragma unroll
    for (int off = 16; off; off >>= 1) sum += __shfl_xor_sync(~0u, sum, off);
    int lo = max(0, i - WINSZ), hi = min(NROWS - 1, i + WINSZ);
    int nband = hi - lo + 1;
    float den = sum + (float)(NROWS - nband) * expf(-m);
    if (lane < BANDW) g_attn[i * BANDW + lane] = e / den;
}

// ---------------- kernel: pack per-layer weights into [128][640] -------------
__global__ void pack_kernel(const float* __restrict__ Wp1, const float* __restrict__ Ws1,
                            const float* __restrict__ Wsa1, const float* __restrict__ Wd1,
                            const float* __restrict__ Wag1,
                            const float* __restrict__ Wp2, const float* __restrict__ Ws2,
                            const float* __restrict__ Wsa2, const float* __restrict__ Wd2,
                            const float* __restrict__ Wag2) {
    int idx = blockIdx.x * blockDim.x + threadIdx.x;
    if (idx >= DIM * YCOLS) return;
    int k = idx / YCOLS, c = idx % YCOLS;
    int rel = c >> 7, d = c & 127;
    const float* s1;
    const float* s2;
    switch (rel) {
        case 0: s1 = Wp1;  s2 = Wp2;  break;
        case 1: s1 = Ws1;  s2 = Ws2;  break;
        case 2: s1 = Wsa1; s2 = Wsa2; break;
        case 3: s1 = Wd1;  s2 = Wd2;  break;
        default: s1 = Wag1; s2 = Wag2; break;
    }
    g_Wcat1[idx] = s1[k * DIM + d];
    g_Wcat2[idx] = s2[k * DIM + d];
}

// ---------------- kernel: 128x128 SGEMM, BK=16, 8x8/thread, reg prefetch -----
template <bool RELU, bool BIAS>
__global__ void __launch_bounds__(256)
sgemm128_kernel(const float* __restrict__ Ax, int Aid,
                const float* __restrict__ Bx, int Bid,
                const float* __restrict__ bias,
                float* __restrict__ Cx, int Cid,
                int M, int N, int K) {
    const float* A = Ax ? Ax : buf_ptr(Aid);
    const float* B = Bx ? Bx : buf_ptr(Bid);
    float* C = Cx ? Cx : buf_ptr(Cid);

    __shared__ float As[16][128];   // transposed A tile: [k][m]
    __shared__ float Bs[16][128];   // [k][n]

    int tid = threadIdx.x;
    int tx = tid & 15, ty = tid >> 4;
    int bm = blockIdx.y * 128, bn = blockIdx.x * 128;

    // A tile: 128x16 floats = 512 float4, 2 per thread
    int af0 = tid * 2, af1 = tid * 2 + 1;
    int ar0 = af0 >> 2, ac0 = (af0 & 3) << 2;
    int ar1 = af1 >> 2, ac1 = (af1 & 3) << 2;
    // B tile: 16x128 floats, 2 float4 per thread
    int br0 = af0 >> 5, bc0 = (af0 & 31) << 2;
    int br1 = af1 >> 5, bc1 = (af1 & 31) << 2;

    float4 pa0 = *(const float4*)&A[(size_t)(bm + ar0) * K + ac0];
    float4 pa1 = *(const float4*)&A[(size_t)(bm + ar1) * K + ac1];
    float4 pb0 = *(const float4*)&B[(size_t)br0 * N + bn + bc0];
    float4 pb1 = *(const float4*)&B[(size_t)br1 * N + bn + bc1];

    float acc[8][8] = {};
    int NK = K >> 4;
    for (int kt = 0; kt < NK; kt++) {
        As[ac0 + 0][ar0] = pa0.x; As[ac0 + 1][ar0] = pa0.y;
        As[ac0 + 2][ar0] = pa0.z; As[ac0 + 3][ar0] = pa0.w;
        As[ac1 + 0][ar1] = pa1.x; As[ac1 + 1][ar1] = pa1.y;
        As[ac1 + 2][ar1] = pa1.z; As[ac1 + 3][ar1] = pa1.w;
        *(float4*)&Bs[br0][bc0] = pb0;
        *(float4*)&Bs[br1][bc1] = pb1;
        __syncthreads();
        if (kt + 1 < NK) {
            int k0 = (kt + 1) << 4;
            pa0 = *(const float4*)&A[(size_t)(bm + ar0) * K + k0 + ac0];
            pa1 = *(const float4*)&A[(size_t)(bm + ar1) * K + k0 + ac1];
            pb0 = *(const float4*)&B[(size_t)(k0 + br0) * N + bn + bc0];
            pb1 = *(const float4*)&B[(size_t)(k0 + br1) * N + bn + bc1];
        }
        #pragma unroll
        for (int k = 0; k < 16; k++) {
            float a[8], b[8];
            *(float4*)&a[0] = *(const float4*)&As[k][ty * 8];
            *(float4*)&a[4] = *(const float4*)&As[k][ty * 8 + 4];
            *(float4*)&b[0] = *(const float4*)&Bs[k][tx * 8];
            *(float4*)&b[4] = *(const float4*)&Bs[k][tx * 8 + 4];
            #pragma unroll
            for (int u = 0; u < 8; u++)
                #pragma unroll
                for (int v = 0; v < 8; v++)
                    acc[u][v] += a[u] * b[v];
        }
        __syncthreads();
    }
    #pragma unroll
    for (int u = 0; u < 8; u++) {
        int row = bm + ty * 8 + u;
        #pragma unroll
        for (int v = 0; v < 8; v += 4) {
            int col = bn + tx * 8 + v;
            float4 val = make_float4(acc[u][v], acc[u][v + 1], acc[u][v + 2], acc[u][v + 3]);
            if (BIAS) {
                val.x += bias[col]; val.y += bias[col + 1];
                val.z += bias[col + 2]; val.w += bias[col + 3];
            }
            if (RELU) {
                val.x = fmaxf(val.x, 0.0f); val.y = fmaxf(val.y, 0.0f);
                val.z = fmaxf(val.z, 0.0f); val.w = fmaxf(val.w, 0.0f);
            }
            *(float4*)&C[(size_t)row * N + col] = val;
        }
    }
}

// ---------------- kernel: tiled SGEMM (BM=BN=64, BK=32, 4x4/thread) ----------
// kept for the head GEMM (N=128: 64x64 tiles give 192 blocks vs 48)
template <bool RELU, bool BIAS>
__global__ void sgemm_kernel(const float* __restrict__ Ax, int Aid,
                             const float* __restrict__ Bx, int Bid,
                             const float* __restrict__ bias,
                             float* __restrict__ Cx, int Cid,
                             int M, int N, int K) {
    const float* A = Ax ? Ax : buf_ptr(Aid);
    const float* B = Bx ? Bx : buf_ptr(Bid);
    float* C = Cx ? Cx : buf_ptr(Cid);

    __shared__ float As[64][36];
    __shared__ float Bs[32][64];

    int tid = threadIdx.x;
    int tx = tid & 15, ty = tid >> 4;
    int bm = blockIdx.y * 64;
    int bn = blockIdx.x * 64;

    float acc[4][4] = {};
    for (int k0 = 0; k0 < K; k0 += 32) {
        {
            int r = tid >> 3;
            int c = (tid & 7) << 2;
            float4 a0 = *(const float4*)&A[(size_t)(bm + r) * K + k0 + c];
            float4 a1 = *(const float4*)&A[(size_t)(bm + r + 32) * K + k0 + c];
            *(float4*)&As[r][c] = a0;
            *(float4*)&As[r + 32][c] = a1;
        }
        {
            int r = tid >> 4;
            int c = (tid & 15) << 2;
            float4 b0 = *(const float4*)&B[(size_t)(k0 + r) * N + bn + c];
            float4 b1 = *(const float4*)&B[(size_t)(k0 + r + 16) * N + bn + c];
            *(float4*)&Bs[r][c] = b0;
            *(float4*)&Bs[r + 16][c] = b1;
        }
        __syncthreads();
        #pragma unroll
        for (int k = 0; k < 32; k++) {
            float a[4];
            #pragma unroll
            for (int u = 0; u < 4; u++) a[u] = As[ty * 4 + u][k];
            float4 bv = *(const float4*)&Bs[k][tx * 4];
            float b[4] = {bv.x, bv.y, bv.z, bv.w};
            #pragma unroll
            for (int u = 0; u < 4; u++)
                #pragma unroll
                for (int v = 0; v < 4; v++)
                    acc[u][v] += a[u] * b[v];
        }
        __syncthreads();
    }
    #pragma unroll
    for (int u = 0; u < 4; u++) {
        int row = bm + ty * 4 + u;
        #pragma unroll
        for (int v = 0; v < 4; v++) {
            int col = bn + tx * 4 + v;
            float val = acc[u][v];
            if (BIAS) val += bias[col];
            if (RELU) val = fmaxf(val, 0.0f);
            C[(size_t)row * N + col] = val;
        }
    }
}

// ---------------- kernel: banded combine + aggr + relu -----------------------
__global__ void combine_kernel(const int* __restrict__ spk, int outid, int out_stride) {
    float* out = buf_ptr(outid);
    int i = blockIdx.x;
    int d = threadIdx.x;

    __shared__ float a_s[BANDW];
    __shared__ int off_s[BANDW];
    if (d < BANDW) {
        int j = i - WINSZ + d;
        float a = 0.0f;
        int off = 0;
        if (j >= 0 && j < NROWS) {
            a = g_attn[i * BANDW + d];
            bool same = (spk[j] == spk[i]);
            bool pred = (d >= WINSZ);
            int col = same ? (pred ? 0 : 1) : (pred ? 2 : 3);
            off = j * YCOLS + col * DIM;
        }
        a_s[d] = a;
        off_s[d] = off;
    }
    __syncthreads();

    float acc = a_s[WINSZ] * g_Y[i * YCOLS + 4 * DIM + d];
    #pragma unroll
    for (int l = 0; l < BANDW; l++) {
        int j = i - WINSZ + l;
        if (j < 0 || j >= NROWS) continue;
        acc += a_s[l] * g_Y[off_s[l] + d];
    }
    out[(size_t)i * out_stride + d] = fmaxf(acc, 0.0f);
}

// ---------------- kernel: emotion / sentiment heads --------------------------
__global__ void head_kernel(const float* __restrict__ we2, const float* __restrict__ be2,
                            const float* __restrict__ ws, const float* __restrict__ bs,
                            float* __restrict__ out) {
    int warp = threadIdx.x >> 5, lane = threadIdx.x & 31;
    int i = blockIdx.x * 8 + warp;
    if (i >= NROWS) return;

    float tv[4];
    #pragma unroll
    for (int c = 0; c < 4; c++) tv[c] = g_T[i * DIM + c * 32 + lane];
    float hv[8];
    #pragma unroll
    for (int c = 0; c < 8; c++) hv[c] = g_Hcat[i * 2 * DIM + c * 32 + lane];

    #pragma unroll
    for (int e = 0; e < NEMO; e++) {
        float s = 0.0f;
        #pragma unroll
        for (int c = 0; c < 4; c++) s += tv[c] * we2[(c * 32 + lane) * NEMO + e];
        #pragma unroll
        for (int off = 16; off; off >>= 1) s += __shfl_xor_sync(~0u, s, off);

        float s2 = 0.0f;
        #pragma unroll
        for (int c = 0; c < 8; c++) s2 += hv[c] * ws[(c * 32 + lane) * NEMO + e];
        #pragma unroll
        for (int off = 16; off; off >>= 1) s2 += __shfl_xor_sync(~0u, s2, off);

        if (lane == 0) {
            out[i * NEMO + e] = s + be2[e];
            out[NROWS * NEMO + i * NEMO + e] = s2 + bs[e];
        }
    }
}

// -----------------------------------------------------------------------------
extern "C" void kernel_launch(void* const* d_in, const int* in_sizes, int n_in,
                              void* d_out, int out_size) {
    const float* x       = (const float*)d_in[0];
    const int*   spk     = (const int*)d_in[1];
    const float* Wp1     = (const float*)d_in[2];
    const float* Ws1     = (const float*)d_in[3];
    const float* Wsa1    = (const float*)d_in[4];
    const float* Wd1     = (const float*)d_in[5];
    const float* Wp2     = (const float*)d_in[6];
    const float* Ws2     = (const float*)d_in[7];
    const float* Wsa2    = (const float*)d_in[8];
    const float* Wd2     = (const float*)d_in[9];
    const float* Wag1    = (const float*)d_in[10];
    const float* Wag2    = (const float*)d_in[11];
    const float* we1     = (const float*)d_in[12];
    const float* be1     = (const float*)d_in[13];
    const float* we2     = (const float*)d_in[14];
    const float* be2     = (const float*)d_in[15];
    const float* wsw     = (const float*)d_in[16];
    const float* bsb     = (const float*)d_in[17];
    float* out = (float*)d_out;

    copyx_kernel<<<(NROWS * DIM + 255) / 256, 256>>>(x);
    attn_kernel<<<NROWS / 4, 128>>>(x);
    pack_kernel<<<(DIM * YCOLS + 255) / 256, 256>>>(Wp1, Ws1, Wsa1, Wd1, Wag1,
                                                    Wp2, Ws2, Wsa2, Wd2, Wag2);
    // Y = x @ Wcat1   (6144x128 @ 128x640)
    sgemm128_kernel<false, false><<<dim3(YCOLS / 128, NROWS / 128), 256>>>(
        x, 0, nullptr, 5, nullptr, nullptr, 1, NROWS, YCOLS, DIM);
    combine_kernel<<<NROWS, DIM>>>(spk, 2, DIM);
    // Y = h1 @ Wcat2
    sgemm128_kernel<false, false><<<dim3(YCOLS / 128, NROWS / 128), 256>>>(
        nullptr, 2, nullptr, 6, nullptr, nullptr, 1, NROWS, YCOLS, DIM);
    combine_kernel<<<NROWS, DIM>>>(spk, 3, 2 * DIM);
    // T = relu(Hcat @ w_e1 + b_e1)   (6144x256 @ 256x128)
    sgemm_kernel<true, true><<<dim3(DIM / 64, NROWS / 64), 256>>>(
        nullptr, 3, we1, 0, be1, nullptr, 4, NROWS, DIM, 2 * DIM);
    head_kernel<<<NROWS / 8, 256>>>(we2, be2, wsw, bsb, out);
}

// round 3
// speedup vs baseline: 1.1256x; 1.1242x over previous
#include <cuda_runtime.h>
#include <math.h>

#define NROWS 6144
#define DIM 128
#define WINSZ 10
#define BANDW 21
#define NEMO 7
#define YCOLS 640   // [W_pred | W_suc | W_same | W_diff | w_aggr] * 128

// ---------------- scratch (device globals; no allocation allowed) ------------
__device__ __align__(16) float g_attn[NROWS * BANDW];
__device__ __align__(16) float g_Wcat1[DIM * YCOLS];
__device__ __align__(16) float g_Wcat2[DIM * YCOLS];
__device__ __align__(16) float g_Y[NROWS * YCOLS];
__device__ __align__(16) float g_H1[NROWS * DIM];
__device__ __align__(16) float g_Hcat[NROWS * 2 * DIM];
__device__ __align__(16) float g_T[NROWS * DIM];

__device__ float* buf_ptr(int id) {
    switch (id) {
        case 1: return g_Y;
        case 2: return g_H1;
        case 3: return g_Hcat;
        case 4: return g_T;
        case 5: return g_Wcat1;
        case 6: return g_Wcat2;
    }
    return nullptr;
}

// ---------------- kernel: copy x into right half of Hcat ---------------------
__global__ void copyx_kernel(const float* __restrict__ x) {
    int idx = blockIdx.x * blockDim.x + threadIdx.x;
    if (idx >= NROWS * DIM) return;
    int i = idx >> 7, d = idx & 127;
    g_Hcat[i * 2 * DIM + DIM + d] = x[idx];
}

// ---------------- kernel: banded scores + faithful softmax -------------------
__global__ void attn_kernel(const float* __restrict__ x) {
    int warp = threadIdx.x >> 5;
    int lane = threadIdx.x & 31;
    int i = blockIdx.x * 4 + warp;
    if (i >= NROWS) return;

    float xi0 = x[i * DIM + lane];
    float xi1 = x[i * DIM + 32 + lane];
    float xi2 = x[i * DIM + 64 + lane];
    float xi3 = x[i * DIM + 96 + lane];

    float myscore = -3.4e38f;
    #pragma unroll
    for (int l = 0; l < BANDW; l++) {
        int j = i - WINSZ + l;
        if (j >= 0 && j < NROWS) {
            const float* xj = x + (size_t)j * DIM;
            float s = xi0 * xj[lane] + xi1 * xj[32 + lane]
                    + xi2 * xj[64 + lane] + xi3 * xj[96 + lane];
            #pragma unroll
            for (int off = 16; off; off >>= 1) s += __shfl_xor_sync(~0u, s, off);
            if (lane == l) myscore = s;
        }
    }
    int jl = i - WINSZ + lane;
    bool valid = (lane < BANDW) && (jl >= 0) && (jl < NROWS);
    float m = valid ? myscore : -3.4e38f;
    #pragma unroll
    for (int off = 16; off; off >>= 1) m = fmaxf(m, __shfl_xor_sync(~0u, m, off));
    m = fmaxf(m, 0.0f);
    float e = valid ? expf(myscore - m) : 0.0f;
    float sum = e;
    #pragma unroll
    for (int off = 16; off; off >>= 1) sum += __shfl_xor_sync(~0u, sum, off);
    int lo = max(0, i - WINSZ), hi = min(NROWS - 1, i + WINSZ);
    int nband = hi - lo + 1;
    float den = sum + (float)(NROWS - nband) * expf(-m);
    if (lane < BANDW) g_attn[i * BANDW + lane] = e / den;
}

// ---------------- kernel: pack per-layer weights into [128][640] -------------
__global__ void pack_kernel(const float* __restrict__ Wp1, const float* __restrict__ Ws1,
                            const float* __restrict__ Wsa1, const float* __restrict__ Wd1,
                            const float* __restrict__ Wag1,
                            const float* __restrict__ Wp2, const float* __restrict__ Ws2,
                            const float* __restrict__ Wsa2, const float* __restrict__ Wd2,
                            const float* __restrict__ Wag2) {
    int idx = blockIdx.x * blockDim.x + threadIdx.x;
    if (idx >= DIM * YCOLS) return;
    int k = idx / YCOLS, c = idx % YCOLS;
    int rel = c >> 7, d = c & 127;
    const float* s1;
    const float* s2;
    switch (rel) {
        case 0: s1 = Wp1;  s2 = Wp2;  break;
        case 1: s1 = Ws1;  s2 = Ws2;  break;
        case 2: s1 = Wsa1; s2 = Wsa2; break;
        case 3: s1 = Wd1;  s2 = Wd2;  break;
        default: s1 = Wag1; s2 = Wag2; break;
    }
    g_Wcat1[idx] = s1[k * DIM + d];
    g_Wcat2[idx] = s2[k * DIM + d];
}

// ------- kernel: 64x64 SGEMM, BK=16, transposed As, double buffer, 4x4 -------
template <bool RELU, bool BIAS>
__global__ void __launch_bounds__(256)
sgemm64_kernel(const float* __restrict__ Ax, int Aid,
               const float* __restrict__ Bx, int Bid,
               const float* __restrict__ bias,
               float* __restrict__ Cx, int Cid,
               int N, int K) {
    const float* A = Ax ? Ax : buf_ptr(Aid);
    const float* B = Bx ? Bx : buf_ptr(Bid);
    float* C = Cx ? Cx : buf_ptr(Cid);

    __shared__ float As[2][16][68];   // [buf][k][m], pad 68 keeps 16B row align
    __shared__ float Bs[2][16][64];   // [buf][k][n]

    int tid = threadIdx.x;
    int tx = tid & 15, ty = tid >> 4;
    int bm = blockIdx.y * 64, bn = blockIdx.x * 64;

    // A tile 64x16: one float4 per thread
    int a_r = tid >> 2, a_c = (tid & 3) << 2;
    // B tile 16x64: one float4 per thread
    int b_r = tid >> 4, b_c = (tid & 15) << 2;

    const float* Ap = A + (size_t)(bm + a_r) * K + a_c;
    const float* Bp = B + (size_t)b_r * N + bn + b_c;

    float4 pa = *(const float4*)Ap;
    float4 pb = *(const float4*)Bp;
    // stage 0
    As[0][a_c + 0][a_r] = pa.x; As[0][a_c + 1][a_r] = pa.y;
    As[0][a_c + 2][a_r] = pa.z; As[0][a_c + 3][a_r] = pa.w;
    *(float4*)&Bs[0][b_r][b_c] = pb;
    __syncthreads();

    float acc[4][4] = {};
    int NK = K >> 4;
    for (int kt = 0; kt < NK; kt++) {
        int buf = kt & 1;
        if (kt + 1 < NK) {
            pa = *(const float4*)(Ap + (kt + 1) * 16);
            pb = *(const float4*)(Bp + (size_t)(kt + 1) * 16 * N);
        }
        #pragma unroll
        for (int k = 0; k < 16; k++) {
            float a[4], b[4];
            *(float4*)a = *(const float4*)&As[buf][k][ty * 4];
            *(float4*)b = *(const float4*)&Bs[buf][k][tx * 4];
            #pragma unroll
            for (int u = 0; u < 4; u++)
                #pragma unroll
                for (int v = 0; v < 4; v++)
                    acc[u][v] += a[u] * b[v];
        }
        if (kt + 1 < NK) {
            int nb = buf ^ 1;
            As[nb][a_c + 0][a_r] = pa.x; As[nb][a_c + 1][a_r] = pa.y;
            As[nb][a_c + 2][a_r] = pa.z; As[nb][a_c + 3][a_r] = pa.w;
            *(float4*)&Bs[nb][b_r][b_c] = pb;
            __syncthreads();
        }
    }
    #pragma unroll
    for (int u = 0; u < 4; u++) {
        int row = bm + ty * 4 + u;
        int col = bn + tx * 4;
        float4 val = make_float4(acc[u][0], acc[u][1], acc[u][2], acc[u][3]);
        if (BIAS) {
            val.x += bias[col]; val.y += bias[col + 1];
            val.z += bias[col + 2]; val.w += bias[col + 3];
        }
        if (RELU) {
            val.x = fmaxf(val.x, 0.0f); val.y = fmaxf(val.y, 0.0f);
            val.z = fmaxf(val.z, 0.0f); val.w = fmaxf(val.w, 0.0f);
        }
        *(float4*)&C[(size_t)row * N + col] = val;
    }
}

// ---------------- kernel: banded combine + aggr + relu (warp/row, float4) ----
__global__ void combine_kernel(const int* __restrict__ spk, int outid, int out_stride) {
    float* out = buf_ptr(outid);
    int warp = threadIdx.x >> 5, lane = threadIdx.x & 31;
    int i = blockIdx.x * 8 + warp;
    if (i >= NROWS) return;

    float a_l = 0.0f;
    int off_l = 0;
    if (lane < BANDW) {
        int j = i - WINSZ + lane;
        if (j >= 0 && j < NROWS) {
            a_l = g_attn[i * BANDW + lane];
            bool same = (spk[j] == spk[i]);
            bool pred = (lane >= WINSZ);
            int col = same ? (pred ? 0 : 1) : (pred ? 2 : 3);
            off_l = j * YCOLS + col * DIM;
        }
    }

    const float4* Yv = (const float4*)g_Y;
    float da = __shfl_sync(~0u, a_l, WINSZ);
    float4 yv = Yv[(i * YCOLS + 4 * DIM) / 4 + lane];
    float4 acc = make_float4(da * yv.x, da * yv.y, da * yv.z, da * yv.w);

    #pragma unroll
    for (int l = 0; l < BANDW; l++) {
        float a = __shfl_sync(~0u, a_l, l);
        int off = __shfl_sync(~0u, off_l, l);
        if (a != 0.0f) {
            float4 y = Yv[off / 4 + lane];
            acc.x += a * y.x; acc.y += a * y.y;
            acc.z += a * y.z; acc.w += a * y.w;
        }
    }
    acc.x = fmaxf(acc.x, 0.0f); acc.y = fmaxf(acc.y, 0.0f);
    acc.z = fmaxf(acc.z, 0.0f); acc.w = fmaxf(acc.w, 0.0f);
    *(float4*)&out[(size_t)i * out_stride + lane * 4] = acc;
}

// ---------------- kernel: emotion / sentiment heads --------------------------
__global__ void head_kernel(const float* __restrict__ we2, const float* __restrict__ be2,
                            const float* __restrict__ ws, const float* __restrict__ bs,
                            float* __restrict__ out) {
    int warp = threadIdx.x >> 5, lane = threadIdx.x & 31;
    int i = blockIdx.x * 8 + warp;
    if (i >= NROWS) return;

    float tv[4];
    #pragma unroll
    for (int c = 0; c < 4; c++) tv[c] = g_T[i * DIM + c * 32 + lane];
    float hv[8];
    #pragma unroll
    for (int c = 0; c < 8; c++) hv[c] = g_Hcat[i * 2 * DIM + c * 32 + lane];

    #pragma unroll
    for (int e = 0; e < NEMO; e++) {
        float s = 0.0f;
        #pragma unroll
        for (int c = 0; c < 4; c++) s += tv[c] * we2[(c * 32 + lane) * NEMO + e];
        #pragma unroll
        for (int off = 16; off; off >>= 1) s += __shfl_xor_sync(~0u, s, off);

        float s2 = 0.0f;
        #pragma unroll
        for (int c = 0; c < 8; c++) s2 += hv[c] * ws[(c * 32 + lane) * NEMO + e];
        #pragma unroll
        for (int off = 16; off; off >>= 1) s2 += __shfl_xor_sync(~0u, s2, off);

        if (lane == 0) {
            out[i * NEMO + e] = s + be2[e];
            out[NROWS * NEMO + i * NEMO + e] = s2 + bs[e];
        }
    }
}

// -----------------------------------------------------------------------------
extern "C" void kernel_launch(void* const* d_in, const int* in_sizes, int n_in,
                              void* d_out, int out_size) {
    const float* x       = (const float*)d_in[0];
    const int*   spk     = (const int*)d_in[1];
    const float* Wp1     = (const float*)d_in[2];
    const float* Ws1     = (const float*)d_in[3];
    const float* Wsa1    = (const float*)d_in[4];
    const float* Wd1     = (const float*)d_in[5];
    const float* Wp2     = (const float*)d_in[6];
    const float* Ws2     = (const float*)d_in[7];
    const float* Wsa2    = (const float*)d_in[8];
    const float* Wd2     = (const float*)d_in[9];
    const float* Wag1    = (const float*)d_in[10];
    const float* Wag2    = (const float*)d_in[11];
    const float* we1     = (const float*)d_in[12];
    const float* be1     = (const float*)d_in[13];
    const float* we2     = (const float*)d_in[14];
    const float* be2     = (const float*)d_in[15];
    const float* wsw     = (const float*)d_in[16];
    const float* bsb     = (const float*)d_in[17];
    float* out = (float*)d_out;

    copyx_kernel<<<(NROWS * DIM + 255) / 256, 256>>>(x);
    attn_kernel<<<NROWS / 4, 128>>>(x);
    pack_kernel<<<(DIM * YCOLS + 255) / 256, 256>>>(Wp1, Ws1, Wsa1, Wd1, Wag1,
                                                    Wp2, Ws2, Wsa2, Wd2, Wag2);
    // Y = x @ Wcat1   (6144x128 @ 128x640)
    sgemm64_kernel<false, false><<<dim3(YCOLS / 64, NROWS / 64), 256>>>(
        x, 0, nullptr, 5, nullptr, nullptr, 1, YCOLS, DIM);
    combine_kernel<<<NROWS / 8, 256>>>(spk, 2, DIM);
    // Y = h1 @ Wcat2
    sgemm64_kernel<false, false><<<dim3(YCOLS / 64, NROWS / 64), 256>>>(
        nullptr, 2, nullptr, 6, nullptr, nullptr, 1, YCOLS, DIM);
    combine_kernel<<<NROWS / 8, 256>>>(spk, 3, 2 * DIM);
    // T = relu(Hcat @ w_e1 + b_e1)   (6144x256 @ 256x128)
    sgemm64_kernel<true, true><<<dim3(DIM / 64, NROWS / 64), 256>>>(
        nullptr, 3, we1, 0, be1, nullptr, 4, DIM, 2 * DIM);
    head_kernel<<<NROWS / 8, 256>>>(we2, be2, wsw, bsb, out);
}

// round 6
// speedup vs baseline: 1.4359x; 1.2757x over previous
#include <cuda_runtime.h>
#include <cuda_bf16.h>
#include <mma.h>
#include <math.h>
#include <stdint.h>

using namespace nvcuda;

#define NROWS 6144
#define DIM 128
#define WINSZ 10
#define BANDW 21
#define NEMO 7
#define YCOLS 640        // [W_pred | W_suc | W_same | W_diff | w_aggr] * 128
#define MT 128           // GEMM M tile
#define NT 64            // GEMM N tile
#define MTILES 48        // 6144/128
#define NTILES 10        // 640/64
#define LDS_PAD 136      // smem row stride in bf16 elems (128 + 8)

// dynamic smem: Ah(128) + Al(128) + Bh(64) + Bl(64) rows * 136 * 2B
#define WG_SMEM ((128 + 128 + 64 + 64) * LDS_PAD * 2)

// ---------------- scratch (device globals; no allocation allowed) ------------
__device__ __align__(16) float g_attn[NROWS * BANDW];
__device__ __align__(16) float g_Y[NROWS * YCOLS];
__device__ __align__(16) float g_Hcat[NROWS * 2 * DIM];
__device__ __align__(16) float g_T[NROWS * DIM];
// hi/lo bf16 splits, plain row-major [row][k], k contiguous
__device__ __align__(16) __nv_bfloat16 g_Ah[NROWS * DIM];
__device__ __align__(16) __nv_bfloat16 g_Al[NROWS * DIM];
__device__ __align__(16) __nv_bfloat16 g_Bh1[YCOLS * DIM];
__device__ __align__(16) __nv_bfloat16 g_Bl1[YCOLS * DIM];
__device__ __align__(16) __nv_bfloat16 g_Bh2[YCOLS * DIM];
__device__ __align__(16) __nv_bfloat16 g_Bl2[YCOLS * DIM];

// ---------------- helpers ----------------------------------------------------
__device__ __forceinline__ void bf_split(float f, uint16_t& h, uint16_t& l) {
    __nv_bfloat16 bh = __float2bfloat16_rn(f);
    float r = f - __bfloat162float(bh);
    __nv_bfloat16 bl = __float2bfloat16_rn(r);
    h = *(uint16_t*)&bh;
    l = *(uint16_t*)&bl;
}
// split 4 floats; write 8B hi chunk + 8B lo chunk
__device__ __forceinline__ void split_store4(char* hp, char* lp, float4 v) {
    uint16_t h0, h1, h2, h3, l0, l1, l2, l3;
    bf_split(v.x, h0, l0); bf_split(v.y, h1, l1);
    bf_split(v.z, h2, l2); bf_split(v.w, h3, l3);
    *(uint2*)hp = make_uint2((uint32_t)h0 | ((uint32_t)h1 << 16),
                             (uint32_t)h2 | ((uint32_t)h3 << 16));
    *(uint2*)lp = make_uint2((uint32_t)l0 | ((uint32_t)l1 << 16),
                             (uint32_t)l2 | ((uint32_t)l3 << 16));
}

// ---------------- kernel: copy x into right half of Hcat ---------------------
__global__ void copyx_kernel(const float* __restrict__ x) {
    int idx = blockIdx.x * blockDim.x + threadIdx.x;
    if (idx >= NROWS * DIM) return;
    int i = idx >> 7, d = idx & 127;
    g_Hcat[i * 2 * DIM + DIM + d] = x[idx];
}

// ---------------- kernel: banded scores + faithful softmax -------------------
__global__ void attn_kernel(const float* __restrict__ x) {
    int warp = threadIdx.x >> 5;
    int lane = threadIdx.x & 31;
    int i = blockIdx.x * 4 + warp;
    if (i >= NROWS) return;

    float xi0 = x[i * DIM + lane];
    float xi1 = x[i * DIM + 32 + lane];
    float xi2 = x[i * DIM + 64 + lane];
    float xi3 = x[i * DIM + 96 + lane];

    float myscore = -3.4e38f;
    #pragma unroll
    for (int l = 0; l < BANDW; l++) {
        int j = i - WINSZ + l;
        if (j >= 0 && j < NROWS) {
            const float* xj = x + (size_t)j * DIM;
            float s = xi0 * xj[lane] + xi1 * xj[32 + lane]
                    + xi2 * xj[64 + lane] + xi3 * xj[96 + lane];
            #pragma unroll
            for (int off = 16; off; off >>= 1) s += __shfl_xor_sync(~0u, s, off);
            if (lane == l) myscore = s;
        }
    }
    int jl = i - WINSZ + lane;
    bool valid = (lane < BANDW) && (jl >= 0) && (jl < NROWS);
    float m = valid ? myscore : -3.4e38f;
    #pragma unroll
    for (int off = 16; off; off >>= 1) m = fmaxf(m, __shfl_xor_sync(~0u, m, off));
    m = fmaxf(m, 0.0f);
    float e = valid ? expf(myscore - m) : 0.0f;
    float sum = e;
    #pragma unroll
    for (int off = 16; off; off >>= 1) sum += __shfl_xor_sync(~0u, sum, off);
    int lo = max(0, i - WINSZ), hi = min(NROWS - 1, i + WINSZ);
    int nband = hi - lo + 1;
    float den = sum + (float)(NROWS - nband) * expf(-m);
    if (lane < BANDW) g_attn[i * BANDW + lane] = e / den;
}

// ------- kernel: pack weights -> bf16 hi/lo, layout [n(640)][k(128)] ---------
__global__ void pack_kernel(const float* __restrict__ Wp1, const float* __restrict__ Ws1,
                            const float* __restrict__ Wsa1, const float* __restrict__ Wd1,
                            const float* __restrict__ Wag1,
                            const float* __restrict__ Wp2, const float* __restrict__ Ws2,
                            const float* __restrict__ Wsa2, const float* __restrict__ Wd2,
                            const float* __restrict__ Wag2) {
    int idx = blockIdx.x * blockDim.x + threadIdx.x;   // over 640*128
    if (idx >= YCOLS * DIM) return;
    int n = idx >> 7, k = idx & 127;                   // n = output col, k = input dim
    int rel = n >> 7, d = n & 127;
    const float* s1;
    const float* s2;
    switch (rel) {
        case 0: s1 = Wp1;  s2 = Wp2;  break;
        case 1: s1 = Ws1;  s2 = Ws2;  break;
        case 2: s1 = Wsa1; s2 = Wsa2; break;
        case 3: s1 = Wd1;  s2 = Wd2;  break;
        default: s1 = Wag1; s2 = Wag2; break;
    }
    uint16_t h, l;
    bf_split(s1[k * DIM + d], h, l);
    *(uint16_t*)&g_Bh1[idx] = h;
    *(uint16_t*)&g_Bl1[idx] = l;
    bf_split(s2[k * DIM + d], h, l);
    *(uint16_t*)&g_Bh2[idx] = h;
    *(uint16_t*)&g_Bl2[idx] = l;
}

// ------- kernel: convert x -> A hi/lo ----------------------------------------
__global__ void convA_kernel(const float* __restrict__ x) {
    int t = blockIdx.x * blockDim.x + threadIdx.x;    // over 6144*32
    if (t >= NROWS * 32) return;
    float4 v = ((const float4*)x)[t];
    size_t byt = (size_t)t * 16;                      // 4 elems * 2B * ... (t*4 elems)
    split_store4((char*)g_Ah + (size_t)t * 8, (char*)g_Al + (size_t)t * 8, v);
    (void)byt;
}

// ------- kernel: wmma bf16-split GEMM  Y[6144x640] = A @ B^T -----------------
// grid (NTILES, MTILES), 256 threads = 8 warps (4 m x 2 n), warp tile 32x32.
// A: g_Ah/g_Al [row][k].  B: [n][k] (so B(k,n) = Bs[n][k] -> wmma col_major).
__global__ void __launch_bounds__(256, 2)
wgemm_kernel(const __nv_bfloat16* __restrict__ Bh,
             const __nv_bfloat16* __restrict__ Bl) {
    extern __shared__ __nv_bfloat16 sm[];
    __nv_bfloat16* Ah_s = sm;                               // 128 x 136
    __nv_bfloat16* Al_s = Ah_s + 128 * LDS_PAD;
    __nv_bfloat16* Bh_s = Al_s + 128 * LDS_PAD;             // 64 x 136
    __nv_bfloat16* Bl_s = Bh_s + 64 * LDS_PAD;

    int tid = threadIdx.x;
    int ntile = blockIdx.x, mtile = blockIdx.y;

    // ---- load tiles (float4 = 8 bf16) ----
    {
        const float4* ga_h = (const float4*)(g_Ah + (size_t)mtile * MT * DIM);
        const float4* ga_l = (const float4*)(g_Al + (size_t)mtile * MT * DIM);
        #pragma unroll
        for (int it = 0; it < 8; it++) {                    // 2048 float4 for A pair
            int v = tid + it * 256;                         // over 128*16
            int row = v >> 4, q = v & 15;
            *(float4*)&Ah_s[row * LDS_PAD + q * 8] = ga_h[v];
            *(float4*)&Al_s[row * LDS_PAD + q * 8] = ga_l[v];
        }
        const float4* gb_h = (const float4*)(Bh + (size_t)ntile * NT * DIM);
        const float4* gb_l = (const float4*)(Bl + (size_t)ntile * NT * DIM);
        #pragma unroll
        for (int it = 0; it < 4; it++) {                    // 1024 float4 for B pair
            int v = tid + it * 256;                         // over 64*16
            int row = v >> 4, q = v & 15;
            *(float4*)&Bh_s[row * LDS_PAD + q * 8] = gb_h[v];
            *(float4*)&Bl_s[row * LDS_PAD + q * 8] = gb_l[v];
        }
    }
    __syncthreads();

    int warp = tid >> 5;
    int wm = warp & 3;            // m offset = wm*32
    int wn = warp >> 2;           // n offset = wn*32

    wmma::fragment<wmma::accumulator, 16, 16, 16, float> acc[2][2];
    #pragma unroll
    for (int u = 0; u < 2; u++)
        #pragma unroll
        for (int v = 0; v < 2; v++) wmma::fill_fragment(acc[u][v], 0.0f);

    #pragma unroll
    for (int ks = 0; ks < 8; ks++) {
        wmma::fragment<wmma::matrix_a, 16, 16, 16, __nv_bfloat16, wmma::row_major> ah[2], al[2];
        wmma::fragment<wmma::matrix_b, 16, 16, 16, __nv_bfloat16, wmma::col_major> bh[2], bl[2];
        #pragma unroll
        for (int u = 0; u < 2; u++) {
            int r = wm * 32 + u * 16;
            wmma::load_matrix_sync(ah[u], &Ah_s[r * LDS_PAD + ks * 16], LDS_PAD);
            wmma::load_matrix_sync(al[u], &Al_s[r * LDS_PAD + ks * 16], LDS_PAD);
        }
        #pragma unroll
        for (int v = 0; v < 2; v++) {
            int r = wn * 32 + v * 16;
            wmma::load_matrix_sync(bh[v], &Bh_s[r * LDS_PAD + ks * 16], LDS_PAD);
            wmma::load_matrix_sync(bl[v], &Bl_s[r * LDS_PAD + ks * 16], LDS_PAD);
        }
        #pragma unroll
        for (int u = 0; u < 2; u++)
            #pragma unroll
            for (int v = 0; v < 2; v++) {
                wmma::mma_sync(acc[u][v], ah[u], bh[v], acc[u][v]);
                wmma::mma_sync(acc[u][v], ah[u], bl[v], acc[u][v]);
                wmma::mma_sync(acc[u][v], al[u], bh[v], acc[u][v]);
            }
    }

    #pragma unroll
    for (int u = 0; u < 2; u++)
        #pragma unroll
        for (int v = 0; v < 2; v++) {
            int row = mtile * MT + wm * 32 + u * 16;
            int col = ntile * NT + wn * 32 + v * 16;
            wmma::store_matrix_sync(&g_Y[(size_t)row * YCOLS + col], acc[u][v],
                                    YCOLS, wmma::mem_row_major);
        }
}

// ------- kernel: banded combine + aggr + relu (warp/row, float4) -------------
// MODE 0: write bf16 hi/lo A (for next GEMM). MODE 1: write Hcat[:,0:128].
template <int MODE>
__global__ void combine_kernel(const int* __restrict__ spk) {
    int warp = threadIdx.x >> 5, lane = threadIdx.x & 31;
    int i = blockIdx.x * 8 + warp;
    if (i >= NROWS) return;

    float a_l = 0.0f;
    int off_l = 0;
    if (lane < BANDW) {
        int j = i - WINSZ + lane;
        if (j >= 0 && j < NROWS) {
            a_l = g_attn[i * BANDW + lane];
            bool same = (spk[j] == spk[i]);
            bool pred = (lane >= WINSZ);
            int col = same ? (pred ? 0 : 1) : (pred ? 2 : 3);
            off_l = j * YCOLS + col * DIM;
        }
    }

    const float4* Yv = (const float4*)g_Y;
    float da = __shfl_sync(~0u, a_l, WINSZ);
    float4 yv = Yv[(i * YCOLS + 4 * DIM) / 4 + lane];
    float4 acc = make_float4(da * yv.x, da * yv.y, da * yv.z, da * yv.w);

    #pragma unroll
    for (int l = 0; l < BANDW; l++) {
        float a = __shfl_sync(~0u, a_l, l);
        int off = __shfl_sync(~0u, off_l, l);
        if (a != 0.0f) {
            float4 y = Yv[off / 4 + lane];
            acc.x += a * y.x; acc.y += a * y.y;
            acc.z += a * y.z; acc.w += a * y.w;
        }
    }
    acc.x = fmaxf(acc.x, 0.0f); acc.y = fmaxf(acc.y, 0.0f);
    acc.z = fmaxf(acc.z, 0.0f); acc.w = fmaxf(acc.w, 0.0f);

    if (MODE == 0) {
        size_t e = (size_t)i * DIM + lane * 4;           // elem index
        split_store4((char*)g_Ah + e * 2, (char*)g_Al + e * 2, acc);
    } else {
        *(float4*)&g_Hcat[(size_t)i * 2 * DIM + lane * 4] = acc;
    }
}

// ------- kernel: head GEMM T = relu(Hcat @ we1 + be1)  (64x64 SIMT) ----------
__global__ void __launch_bounds__(256)
headgemm_kernel(const float* __restrict__ B, const float* __restrict__ bias) {
    const int N = DIM, K = 2 * DIM;
    const float* A = g_Hcat;
    float* C = g_T;

    __shared__ float As[2][16][68];
    __shared__ float Bs[2][16][64];

    int tid = threadIdx.x;
    int tx = tid & 15, ty = tid >> 4;
    int bm = blockIdx.y * 64, bn = blockIdx.x * 64;

    int a_r = tid >> 2, a_c = (tid & 3) << 2;
    int b_r = tid >> 4, b_c = (tid & 15) << 2;

    const float* Ap = A + (size_t)(bm + a_r) * K + a_c;
    const float* Bp = B + (size_t)b_r * N + bn + b_c;

    float4 pa = *(const float4*)Ap;
    float4 pb = *(const float4*)Bp;
    As[0][a_c + 0][a_r] = pa.x; As[0][a_c + 1][a_r] = pa.y;
    As[0][a_c + 2][a_r] = pa.z; As[0][a_c + 3][a_r] = pa.w;
    *(float4*)&Bs[0][b_r][b_c] = pb;
    __syncthreads();

    float acc[4][4] = {};
    int NK = K >> 4;
    for (int kt = 0; kt < NK; kt++) {
        int buf = kt & 1;
        if (kt + 1 < NK) {
            pa = *(const float4*)(Ap + (kt + 1) * 16);
            pb = *(const float4*)(Bp + (size_t)(kt + 1) * 16 * N);
        }
        #pragma unroll
        for (int k = 0; k < 16; k++) {
            float a[4], b[4];
            *(float4*)a = *(const float4*)&As[buf][k][ty * 4];
            *(float4*)b = *(const float4*)&Bs[buf][k][tx * 4];
            #pragma unroll
            for (int u = 0; u < 4; u++)
                #pragma unroll
                for (int v = 0; v < 4; v++)
                    acc[u][v] += a[u] * b[v];
        }
        if (kt + 1 < NK) {
            int nb = buf ^ 1;
            As[nb][a_c + 0][a_r] = pa.x; As[nb][a_c + 1][a_r] = pa.y;
            As[nb][a_c + 2][a_r] = pa.z; As[nb][a_c + 3][a_r] = pa.w;
            *(float4*)&Bs[nb][b_r][b_c] = pb;
            __syncthreads();
        }
    }
    #pragma unroll
    for (int u = 0; u < 4; u++) {
        int row = bm + ty * 4 + u;
        int col = bn + tx * 4;
        float4 val = make_float4(acc[u][0] + bias[col], acc[u][1] + bias[col + 1],
                                 acc[u][2] + bias[col + 2], acc[u][3] + bias[col + 3]);
        val.x = fmaxf(val.x, 0.0f); val.y = fmaxf(val.y, 0.0f);
        val.z = fmaxf(val.z, 0.0f); val.w = fmaxf(val.w, 0.0f);
        *(float4*)&C[(size_t)row * N + col] = val;
    }
}

// ---------------- kernel: emotion / sentiment heads --------------------------
__global__ void head_kernel(const float* __restrict__ we2, const float* __restrict__ be2,
                            const float* __restrict__ ws, const float* __restrict__ bs,
                            float* __restrict__ out) {
    int warp = threadIdx.x >> 5, lane = threadIdx.x & 31;
    int i = blockIdx.x * 8 + warp;
    if (i >= NROWS) return;

    float tv[4];
    #pragma unroll
    for (int c = 0; c < 4; c++) tv[c] = g_T[i * DIM + c * 32 + lane];
    float hv[8];
    #pragma unroll
    for (int c = 0; c < 8; c++) hv[c] = g_Hcat[i * 2 * DIM + c * 32 + lane];

    #pragma unroll
    for (int e = 0; e < NEMO; e++) {
        float s = 0.0f;
        #pragma unroll
        for (int c = 0; c < 4; c++) s += tv[c] * we2[(c * 32 + lane) * NEMO + e];
        #pragma unroll
        for (int off = 16; off; off >>= 1) s += __shfl_xor_sync(~0u, s, off);

        float s2 = 0.0f;
        #pragma unroll
        for (int c = 0; c < 8; c++) s2 += hv[c] * ws[(c * 32 + lane) * NEMO + e];
        #pragma unroll
        for (int off = 16; off; off >>= 1) s2 += __shfl_xor_sync(~0u, s2, off);

        if (lane == 0) {
            out[i * NEMO + e] = s + be2[e];
            out[NROWS * NEMO + i * NEMO + e] = s2 + bs[e];
        }
    }
}

// -----------------------------------------------------------------------------
extern "C" void kernel_launch(void* const* d_in, const int* in_sizes, int n_in,
                              void* d_out, int out_size) {
    const float* x       = (const float*)d_in[0];
    const int*   spk     = (const int*)d_in[1];
    const float* Wp1     = (const float*)d_in[2];
    const float* Ws1     = (const float*)d_in[3];
    const float* Wsa1    = (const float*)d_in[4];
    const float* Wd1     = (const float*)d_in[5];
    const float* Wp2     = (const float*)d_in[6];
    const float* Ws2     = (const float*)d_in[7];
    const float* Wsa2    = (const float*)d_in[8];
    const float* Wd2     = (const float*)d_in[9];
    const float* Wag1    = (const float*)d_in[10];
    const float* Wag2    = (const float*)d_in[11];
    const float* we1     = (const float*)d_in[12];
    const float* be1     = (const float*)d_in[13];
    const float* we2     = (const float*)d_in[14];
    const float* be2     = (const float*)d_in[15];
    const float* wsw     = (const float*)d_in[16];
    const float* bsb     = (const float*)d_in[17];
    float* out = (float*)d_out;

    cudaFuncSetAttribute(wgemm_kernel,
                         cudaFuncAttributeMaxDynamicSharedMemorySize, WG_SMEM);

    // resolve device addresses of the weight blobs for kernel args
    __nv_bfloat16 *bh1, *bl1, *bh2, *bl2;
    cudaGetSymbolAddress((void**)&bh1, g_Bh1);
    cudaGetSymbolAddress((void**)&bl1, g_Bl1);
    cudaGetSymbolAddress((void**)&bh2, g_Bh2);
    cudaGetSymbolAddress((void**)&bl2, g_Bl2);

    copyx_kernel<<<(NROWS * DIM + 255) / 256, 256>>>(x);
    attn_kernel<<<NROWS / 4, 128>>>(x);
    pack_kernel<<<(YCOLS * DIM + 255) / 256, 256>>>(Wp1, Ws1, Wsa1, Wd1, Wag1,
                                                    Wp2, Ws2, Wsa2, Wd2, Wag2);
    convA_kernel<<<(NROWS * 32 + 255) / 256, 256>>>(x);
    // Y = x @ Wcat1
    wgemm_kernel<<<dim3(NTILES, MTILES), 256, WG_SMEM>>>(bh1, bl1);
    combine_kernel<0><<<NROWS / 8, 256>>>(spk);   // -> A hi/lo (h1)
    // Y = h1 @ Wcat2
    wgemm_kernel<<<dim3(NTILES, MTILES), 256, WG_SMEM>>>(bh2, bl2);
    combine_kernel<1><<<NROWS / 8, 256>>>(spk);   // -> Hcat[:,0:128]
    // T = relu(Hcat @ we1 + be1)
    headgemm_kernel<<<dim3(DIM / 64, NROWS / 64), 256>>>(we1, be1);
    head_kernel<<<NROWS / 8, 256>>>(we2, be2, wsw, bsb, out);
}

// round 7
// speedup vs baseline: 1.5485x; 1.0784x over previous
#include <cuda_runtime.h>
#include <cuda_bf16.h>
#include <mma.h>
#include <math.h>
#include <stdint.h>

using namespace nvcuda;

#define NROWS 6144
#define DIM 128
#define WINSZ 10
#define BANDW 21
#define NEMO 7
#define YCOLS 640        // [W_pred | W_suc | W_same | W_diff | w_aggr] * 128
#define MT 128           // GEMM M tile
#define NT 64            // GEMM N tile
#define MTILES 48        // 6144/128
#define NTILES 10        // 640/64
#define LDS_PAD 136      // smem row stride in bf16 elems (128 + 8)

// dynamic smem: Ah(128) + Al(128) + Bh(64) + Bl(64) rows * 136 * 2B
#define WG_SMEM ((128 + 128 + 64 + 64) * LDS_PAD * 2)

// ---------------- scratch (device globals; no allocation allowed) ------------
__device__ __align__(16) float g_attn[NROWS * BANDW];
__device__ __align__(16) float g_Y[NROWS * YCOLS];
__device__ __align__(16) float g_Hcat[NROWS * 2 * DIM];
__device__ __align__(16) float g_T[NROWS * DIM];
// bf16 hi/lo splits, row-major, k contiguous
__device__ __align__(16) __nv_bfloat16 g_Ah[NROWS * DIM];        // h1 split
__device__ __align__(16) __nv_bfloat16 g_Al[NROWS * DIM];
__device__ __align__(16) __nv_bfloat16 g_Hh[NROWS * 2 * DIM];    // Hcat split
__device__ __align__(16) __nv_bfloat16 g_Hl[NROWS * 2 * DIM];
__device__ __align__(16) __nv_bfloat16 g_Bh1[YCOLS * DIM];
__device__ __align__(16) __nv_bfloat16 g_Bl1[YCOLS * DIM];
__device__ __align__(16) __nv_bfloat16 g_Bh2[YCOLS * DIM];
__device__ __align__(16) __nv_bfloat16 g_Bl2[YCOLS * DIM];
__device__ __align__(16) __nv_bfloat16 g_Weh[DIM * 2 * DIM];     // we1 split [n=128][k=256]
__device__ __align__(16) __nv_bfloat16 g_Wel[DIM * 2 * DIM];

// ---------------- helpers ----------------------------------------------------
__device__ __forceinline__ void bf_split(float f, uint16_t& h, uint16_t& l) {
    __nv_bfloat16 bh = __float2bfloat16_rn(f);
    float r = f - __bfloat162float(bh);
    __nv_bfloat16 bl = __float2bfloat16_rn(r);
    h = *(uint16_t*)&bh;
    l = *(uint16_t*)&bl;
}
__device__ __forceinline__ void split_store4(char* hp, char* lp, float4 v) {
    uint16_t h0, h1, h2, h3, l0, l1, l2, l3;
    bf_split(v.x, h0, l0); bf_split(v.y, h1, l1);
    bf_split(v.z, h2, l2); bf_split(v.w, h3, l3);
    *(uint2*)hp = make_uint2((uint32_t)h0 | ((uint32_t)h1 << 16),
                             (uint32_t)h2 | ((uint32_t)h3 << 16));
    *(uint2*)lp = make_uint2((uint32_t)l0 | ((uint32_t)l1 << 16),
                             (uint32_t)l2 | ((uint32_t)l3 << 16));
}

// ------- kernel: prep x -> Hcat right half (fp32 + hi/lo split) --------------
__global__ void prep_kernel(const float* __restrict__ x) {
    int t = blockIdx.x * blockDim.x + threadIdx.x;    // over 6144*32
    if (t >= NROWS * 32) return;
    int i = t >> 5, q = t & 31;
    float4 v = ((const float4*)x)[t];
    size_t e = (size_t)i * 2 * DIM + DIM + q * 4;
    *(float4*)&g_Hcat[e] = v;
    split_store4((char*)g_Hh + e * 2, (char*)g_Hl + e * 2, v);
}

// ---------------- kernel: banded scores + faithful softmax -------------------
__global__ void attn_kernel(const float* __restrict__ x) {
    int warp = threadIdx.x >> 5;
    int lane = threadIdx.x & 31;
    int i = blockIdx.x * 4 + warp;
    if (i >= NROWS) return;

    float xi0 = x[i * DIM + lane];
    float xi1 = x[i * DIM + 32 + lane];
    float xi2 = x[i * DIM + 64 + lane];
    float xi3 = x[i * DIM + 96 + lane];

    float myscore = -3.4e38f;
    #pragma unroll
    for (int l = 0; l < BANDW; l++) {
        int j = i - WINSZ + l;
        if (j >= 0 && j < NROWS) {
            const float* xj = x + (size_t)j * DIM;
            float s = xi0 * xj[lane] + xi1 * xj[32 + lane]
                    + xi2 * xj[64 + lane] + xi3 * xj[96 + lane];
            #pragma unroll
            for (int off = 16; off; off >>= 1) s += __shfl_xor_sync(~0u, s, off);
            if (lane == l) myscore = s;
        }
    }
    int jl = i - WINSZ + lane;
    bool valid = (lane < BANDW) && (jl >= 0) && (jl < NROWS);
    float m = valid ? myscore : -3.4e38f;
    #pragma unroll
    for (int off = 16; off; off >>= 1) m = fmaxf(m, __shfl_xor_sync(~0u, m, off));
    m = fmaxf(m, 0.0f);
    float e = valid ? expf(myscore - m) : 0.0f;
    float sum = e;
    #pragma unroll
    for (int off = 16; off; off >>= 1) sum += __shfl_xor_sync(~0u, sum, off);
    int lo = max(0, i - WINSZ), hi = min(NROWS - 1, i + WINSZ);
    int nband = hi - lo + 1;
    float den = sum + (float)(NROWS - nband) * expf(-m);
    if (lane < BANDW) g_attn[i * BANDW + lane] = e / den;
}

// ------- kernel: pack layer weights -> bf16 hi/lo, layout [n(640)][k(128)] ---
__global__ void pack_kernel(const float* __restrict__ Wp1, const float* __restrict__ Ws1,
                            const float* __restrict__ Wsa1, const float* __restrict__ Wd1,
                            const float* __restrict__ Wag1,
                            const float* __restrict__ Wp2, const float* __restrict__ Ws2,
                            const float* __restrict__ Wsa2, const float* __restrict__ Wd2,
                            const float* __restrict__ Wag2) {
    int idx = blockIdx.x * blockDim.x + threadIdx.x;   // over 640*128
    if (idx >= YCOLS * DIM) return;
    int n = idx >> 7, k = idx & 127;
    int rel = n >> 7, d = n & 127;
    const float* s1;
    const float* s2;
    switch (rel) {
        case 0: s1 = Wp1;  s2 = Wp2;  break;
        case 1: s1 = Ws1;  s2 = Ws2;  break;
        case 2: s1 = Wsa1; s2 = Wsa2; break;
        case 3: s1 = Wd1;  s2 = Wd2;  break;
        default: s1 = Wag1; s2 = Wag2; break;
    }
    uint16_t h, l;
    bf_split(s1[k * DIM + d], h, l);
    *(uint16_t*)&g_Bh1[idx] = h;
    *(uint16_t*)&g_Bl1[idx] = l;
    bf_split(s2[k * DIM + d], h, l);
    *(uint16_t*)&g_Bh2[idx] = h;
    *(uint16_t*)&g_Bl2[idx] = l;
}

// ------- kernel: pack we1 [256][128] -> hi/lo blob [n=128][k=256] ------------
__global__ void packE_kernel(const float* __restrict__ we1) {
    int idx = blockIdx.x * blockDim.x + threadIdx.x;   // over 128*256
    if (idx >= DIM * 2 * DIM) return;
    int n = idx >> 8, k = idx & 255;
    uint16_t h, l;
    bf_split(we1[k * DIM + n], h, l);
    *(uint16_t*)&g_Weh[idx] = h;
    *(uint16_t*)&g_Wel[idx] = l;
}

// ------- kernel: wmma bf16-split GEMM  C[M x ...] = A @ B^T ------------------
// grid (n_tiles, m_tiles), 256 threads = 8 warps (4 m x 2 n), warp tile 32x32.
// A: [row][k] hi/lo with row stride lda4*8 elems. B: [n][k] hi/lo, stride ldb4*8.
// KCHUNKS chunks of 128 along k. EPI: bias+relu via smem staging.
template <int KCHUNKS, bool EPI>
__global__ void __launch_bounds__(256, 2)
wgemm_kernel(const __nv_bfloat16* __restrict__ Ah, const __nv_bfloat16* __restrict__ Al,
             int lda4,
             const __nv_bfloat16* __restrict__ Bh, const __nv_bfloat16* __restrict__ Bl,
             int ldb4,
             float* __restrict__ C, int ldc, const float* __restrict__ bias) {
    extern __shared__ __nv_bfloat16 sm[];
    __nv_bfloat16* Ah_s = sm;                               // 128 x 136
    __nv_bfloat16* Al_s = Ah_s + 128 * LDS_PAD;
    __nv_bfloat16* Bh_s = Al_s + 128 * LDS_PAD;             // 64 x 136
    __nv_bfloat16* Bl_s = Bh_s + 64 * LDS_PAD;

    int tid = threadIdx.x;
    int ntile = blockIdx.x, mtile = blockIdx.y;
    int warp = tid >> 5, lane = tid & 31;
    int wm = warp & 3;            // m offset = wm*32
    int wn = warp >> 2;           // n offset = wn*32

    wmma::fragment<wmma::accumulator, 16, 16, 16, float> acc[2][2];
    #pragma unroll
    for (int u = 0; u < 2; u++)
        #pragma unroll
        for (int v = 0; v < 2; v++) wmma::fill_fragment(acc[u][v], 0.0f);

    const float4* ga_h = (const float4*)Ah;
    const float4* ga_l = (const float4*)Al;
    const float4* gb_h = (const float4*)Bh;
    const float4* gb_l = (const float4*)Bl;

    #pragma unroll
    for (int kc = 0; kc < KCHUNKS; kc++) {
        if (kc) __syncthreads();
        #pragma unroll
        for (int it = 0; it < 8; it++) {                    // A pair: 128x16 float4
            int v = tid + it * 256;
            int row = v >> 4, q = v & 15;
            int gi = (mtile * MT + row) * lda4 + kc * 16 + q;
            *(float4*)&Ah_s[row * LDS_PAD + q * 8] = ga_h[gi];
            *(float4*)&Al_s[row * LDS_PAD + q * 8] = ga_l[gi];
        }
        #pragma unroll
        for (int it = 0; it < 4; it++) {                    // B pair: 64x16 float4
            int v = tid + it * 256;
            int row = v >> 4, q = v & 15;
            int gi = (ntile * NT + row) * ldb4 + kc * 16 + q;
            *(float4*)&Bh_s[row * LDS_PAD + q * 8] = gb_h[gi];
            *(float4*)&Bl_s[row * LDS_PAD + q * 8] = gb_l[gi];
        }
        __syncthreads();

        #pragma unroll
        for (int ks = 0; ks < 8; ks++) {
            wmma::fragment<wmma::matrix_a, 16, 16, 16, __nv_bfloat16, wmma::row_major> ah[2], al[2];
            wmma::fragment<wmma::matrix_b, 16, 16, 16, __nv_bfloat16, wmma::col_major> bh[2], bl[2];
            #pragma unroll
            for (int u = 0; u < 2; u++) {
                int r = wm * 32 + u * 16;
                wmma::load_matrix_sync(ah[u], &Ah_s[r * LDS_PAD + ks * 16], LDS_PAD);
                wmma::load_matrix_sync(al[u], &Al_s[r * LDS_PAD + ks * 16], LDS_PAD);
            }
            #pragma unroll
            for (int v = 0; v < 2; v++) {
                int r = wn * 32 + v * 16;
                wmma::load_matrix_sync(bh[v], &Bh_s[r * LDS_PAD + ks * 16], LDS_PAD);
                wmma::load_matrix_sync(bl[v], &Bl_s[r * LDS_PAD + ks * 16], LDS_PAD);
            }
            #pragma unroll
            for (int u = 0; u < 2; u++)
                #pragma unroll
                for (int v = 0; v < 2; v++) {
                    wmma::mma_sync(acc[u][v], ah[u], bh[v], acc[u][v]);
                    wmma::mma_sync(acc[u][v], ah[u], bl[v], acc[u][v]);
                    wmma::mma_sync(acc[u][v], al[u], bh[v], acc[u][v]);
                }
        }
    }

    if (!EPI) {
        #pragma unroll
        for (int u = 0; u < 2; u++)
            #pragma unroll
            for (int v = 0; v < 2; v++) {
                int row = mtile * MT + wm * 32 + u * 16;
                int col = ntile * NT + wn * 32 + v * 16;
                wmma::store_matrix_sync(&C[(size_t)row * ldc + col], acc[u][v],
                                        ldc, wmma::mem_row_major);
            }
    } else {
        // stage per-warp 32x32 in smem, then bias+relu+store
        __syncthreads();
        float* stage = (float*)sm + warp * 1024;
        #pragma unroll
        for (int u = 0; u < 2; u++)
            #pragma unroll
            for (int v = 0; v < 2; v++)
                wmma::store_matrix_sync(&stage[u * 16 * 32 + v * 16], acc[u][v],
                                        32, wmma::mem_row_major);
        int row = mtile * MT + wm * 32 + lane;
        int colbase = ntile * NT + wn * 32;
        #pragma unroll
        for (int c = 0; c < 32; c += 4) {
            float4 val = *(float4*)&stage[lane * 32 + c];
            float4 bv = *(const float4*)&bias[colbase + c];
            val.x = fmaxf(val.x + bv.x, 0.0f);
            val.y = fmaxf(val.y + bv.y, 0.0f);
            val.z = fmaxf(val.z + bv.z, 0.0f);
            val.w = fmaxf(val.w + bv.w, 0.0f);
            *(float4*)&C[(size_t)row * ldc + colbase + c] = val;
        }
    }
}

// ------- kernel: banded combine + aggr + relu (warp/row, float4) -------------
// MODE 0: write bf16 hi/lo A (h1, for layer-2 GEMM).
// MODE 1: write Hcat[:,0:128] fp32 + hi/lo into g_Hh/g_Hl left half.
template <int MODE>
__global__ void combine_kernel(const int* __restrict__ spk) {
    int warp = threadIdx.x >> 5, lane = threadIdx.x & 31;
    int i = blockIdx.x * 8 + warp;
    if (i >= NROWS) return;

    float a_l = 0.0f;
    int off_l = 0;
    if (lane < BANDW) {
        int j = i - WINSZ + lane;
        if (j >= 0 && j < NROWS) {
            a_l = g_attn[i * BANDW + lane];
            bool same = (spk[j] == spk[i]);
            bool pred = (lane >= WINSZ);
            int col = same ? (pred ? 0 : 1) : (pred ? 2 : 3);
            off_l = j * YCOLS + col * DIM;
        }
    }

    const float4* Yv = (const float4*)g_Y;
    float da = __shfl_sync(~0u, a_l, WINSZ);
    float4 yv = Yv[(i * YCOLS + 4 * DIM) / 4 + lane];
    float4 acc = make_float4(da * yv.x, da * yv.y, da * yv.z, da * yv.w);

    #pragma unroll
    for (int l = 0; l < BANDW; l++) {
        float a = __shfl_sync(~0u, a_l, l);
        int off = __shfl_sync(~0u, off_l, l);
        if (a != 0.0f) {
            float4 y = Yv[off / 4 + lane];
            acc.x += a * y.x; acc.y += a * y.y;
            acc.z += a * y.z; acc.w += a * y.w;
        }
    }
    acc.x = fmaxf(acc.x, 0.0f); acc.y = fmaxf(acc.y, 0.0f);
    acc.z = fmaxf(acc.z, 0.0f); acc.w = fmaxf(acc.w, 0.0f);

    if (MODE == 0) {
        size_t e = (size_t)i * DIM + lane * 4;
        split_store4((char*)g_Ah + e * 2, (char*)g_Al + e * 2, acc);
    } else {
        size_t e = (size_t)i * 2 * DIM + lane * 4;
        *(float4*)&g_Hcat[e] = acc;
        split_store4((char*)g_Hh + e * 2, (char*)g_Hl + e * 2, acc);
    }
}

// ---------------- kernel: emotion / sentiment heads --------------------------
__global__ void head_kernel(const float* __restrict__ we2, const float* __restrict__ be2,
                            const float* __restrict__ ws, const float* __restrict__ bs,
                            float* __restrict__ out) {
    int warp = threadIdx.x >> 5, lane = threadIdx.x & 31;
    int i = blockIdx.x * 8 + warp;
    if (i >= NROWS) return;

    float tv[4];
    #pragma unroll
    for (int c = 0; c < 4; c++) tv[c] = g_T[i * DIM + c * 32 + lane];
    float hv[8];
    #pragma unroll
    for (int c = 0; c < 8; c++) hv[c] = g_Hcat[i * 2 * DIM + c * 32 + lane];

    #pragma unroll
    for (int e = 0; e < NEMO; e++) {
        float s = 0.0f;
        #pragma unroll
        for (int c = 0; c < 4; c++) s += tv[c] * we2[(c * 32 + lane) * NEMO + e];
        #pragma unroll
        for (int off = 16; off; off >>= 1) s += __shfl_xor_sync(~0u, s, off);

        float s2 = 0.0f;
        #pragma unroll
        for (int c = 0; c < 8; c++) s2 += hv[c] * ws[(c * 32 + lane) * NEMO + e];
        #pragma unroll
        for (int off = 16; off; off >>= 1) s2 += __shfl_xor_sync(~0u, s2, off);

        if (lane == 0) {
            out[i * NEMO + e] = s + be2[e];
            out[NROWS * NEMO + i * NEMO + e] = s2 + bs[e];
        }
    }
}

// -----------------------------------------------------------------------------
extern "C" void kernel_launch(void* const* d_in, const int* in_sizes, int n_in,
                              void* d_out, int out_size) {
    const float* x       = (const float*)d_in[0];
    const int*   spk     = (const int*)d_in[1];
    const float* Wp1     = (const float*)d_in[2];
    const float* Ws1     = (const float*)d_in[3];
    const float* Wsa1    = (const float*)d_in[4];
    const float* Wd1     = (const float*)d_in[5];
    const float* Wp2     = (const float*)d_in[6];
    const float* Ws2     = (const float*)d_in[7];
    const float* Wsa2    = (const float*)d_in[8];
    const float* Wd2     = (const float*)d_in[9];
    const float* Wag1    = (const float*)d_in[10];
    const float* Wag2    = (const float*)d_in[11];
    const float* we1     = (const float*)d_in[12];
    const float* be1     = (const float*)d_in[13];
    const float* we2     = (const float*)d_in[14];
    const float* be2     = (const float*)d_in[15];
    const float* wsw     = (const float*)d_in[16];
    const float* bsb     = (const float*)d_in[17];
    float* out = (float*)d_out;

    cudaFuncSetAttribute(wgemm_kernel<1, false>,
                         cudaFuncAttributeMaxDynamicSharedMemorySize, WG_SMEM);
    cudaFuncSetAttribute(wgemm_kernel<2, true>,
                         cudaFuncAttributeMaxDynamicSharedMemorySize, WG_SMEM);

    __nv_bfloat16 *ah, *al, *hh, *hl, *bh1, *bl1, *bh2, *bl2, *weh, *wel;
    float *yp, *tp;
    cudaGetSymbolAddress((void**)&ah, g_Ah);
    cudaGetSymbolAddress((void**)&al, g_Al);
    cudaGetSymbolAddress((void**)&hh, g_Hh);
    cudaGetSymbolAddress((void**)&hl, g_Hl);
    cudaGetSymbolAddress((void**)&bh1, g_Bh1);
    cudaGetSymbolAddress((void**)&bl1, g_Bl1);
    cudaGetSymbolAddress((void**)&bh2, g_Bh2);
    cudaGetSymbolAddress((void**)&bl2, g_Bl2);
    cudaGetSymbolAddress((void**)&weh, g_Weh);
    cudaGetSymbolAddress((void**)&wel, g_Wel);
    cudaGetSymbolAddress((void**)&yp, g_Y);
    cudaGetSymbolAddress((void**)&tp, g_T);

    prep_kernel<<<(NROWS * 32 + 255) / 256, 256>>>(x);
    attn_kernel<<<NROWS / 4, 128>>>(x);
    pack_kernel<<<(YCOLS * DIM + 255) / 256, 256>>>(Wp1, Ws1, Wsa1, Wd1, Wag1,
                                                    Wp2, Ws2, Wsa2, Wd2, Wag2);
    packE_kernel<<<(DIM * 2 * DIM + 255) / 256, 256>>>(we1);
    // Y = x @ Wcat1   (A = right half of Hcat split, lda = 256)
    wgemm_kernel<1, false><<<dim3(NTILES, MTILES), 256, WG_SMEM>>>(
        hh + DIM, hl + DIM, 32, bh1, bl1, 16, yp, YCOLS, nullptr);
    combine_kernel<0><<<NROWS / 8, 256>>>(spk);   // -> g_Ah/g_Al (h1)
    // Y = h1 @ Wcat2
    wgemm_kernel<1, false><<<dim3(NTILES, MTILES), 256, WG_SMEM>>>(
        ah, al, 16, bh2, bl2, 16, yp, YCOLS, nullptr);
    combine_kernel<1><<<NROWS / 8, 256>>>(spk);   // -> Hcat left + split
    // T = relu(Hcat @ we1 + be1)   (K = 256 -> 2 chunks)
    wgemm_kernel<2, true><<<dim3(2, MTILES), 256, WG_SMEM>>>(
        hh, hl, 32, weh, wel, 32, tp, DIM, be1);
    head_kernel<<<NROWS / 8, 256>>>(we2, be2, wsw, bsb, out);
}